// round 11
// baseline (speedup 1.0000x reference)
#include <cuda_runtime.h>
#include <cuda_bf16.h>
#include <cuda_fp16.h>

// Shapes (fixed by setup_inputs): B=32, T=512, C=T-1=511, K=8, S=8, d=300
#define BB 32
#define CC 511
#define KK 8
#define SS 8
#define DD 300
#define D4 75      // DD/4 float4 per row
#define D2 150     // DD/2 float2 per row
#define TILE_C 32
#define NSPLIT 16  // ceil(511/32); power of 2 for wrapping counter
#define RSQRT300 0.057735026918962576f

// Scratch (device globals; no allocation allowed)
__device__ float g_pden[BB * NSPLIT * KK];        // partial sum of exp(a)
__device__ float g_mpart[BB * NSPLIT * KK * DD];  // partial unnormalized m'
__device__ unsigned g_cnt[BB];                    // wrapping completion counters

// ---------------------------------------------------------------------------
// Single fused kernel. grid (NSPLIT=16, B=32) = 512 blocks, block 256.
// R10 structure, but center tile held in smem as half2 (4.8KB instead of
// 9.6KB) so smem = 44.2KB <= 45.6KB, enabling 5 CTAs/SM together with
// __launch_bounds__(256,5) (51 regs). fp16 touches ONLY the softmax-logit
// dot (error ~1e-4, tolerance 1e-3); v/mean/m'/cosine all stay fp32.
// ---------------------------------------------------------------------------
__global__ __launch_bounds__(256, 5) void k_main(const float* __restrict__ ctx,
                                                 const float* __restrict__ center,
                                                 float* __restrict__ out) {
    const int b = blockIdx.y;
    const int tile = blockIdx.x;
    __shared__ uint2 cenh[KK * D4];        // 4800 B: half2-packed center
    __shared__ float4 vt[TILE_C * D4];     // 38400 B
    __shared__ float ew[KK][TILE_C];       // 1024 B   (total 44224 B)

    {
        // pack center fp32 -> half2 pairs; uint2 = 4 halves = one float4 slot
        const float4* cg = reinterpret_cast<const float4*>(center + (size_t)b * KK * DD);
        for (int i = threadIdx.x; i < KK * D4; i += blockDim.x) {
            float4 v = cg[i];
            __half2 h0 = __floats2half2_rn(v.x, v.y);
            __half2 h1 = __floats2half2_rn(v.z, v.w);
            uint2 u;
            u.x = *reinterpret_cast<unsigned*>(&h0);
            u.y = *reinterpret_cast<unsigned*>(&h1);
            cenh[i] = u;
        }
    }
    __syncthreads();

    const int w = threadIdx.x >> 5;
    const int lane = threadIdx.x & 31;
    const int j0 = lane, j1 = lane + 32, j2 = lane + 64;
    const bool p2 = (j2 < D4);

    const int c0 = tile * TILE_C;
    int cn = CC - c0; if (cn > TILE_C) cn = TILE_C;

    // ---- Phase A: warp per c; v=mean_s -> smem; fused dots, serial per-k ----
    for (int ci = w; ci < cn; ci += 8) {
        const int c = c0 + ci;
        const float4* p = reinterpret_cast<const float4*>(ctx) + (size_t)(b * CC + c) * (SS * D4);
        float4 a0 = {0.f, 0.f, 0.f, 0.f}, a1 = a0, a2 = a0;
#pragma unroll
        for (int s = 0; s < SS; s++) {
            const float4* ps = p + s * D4;
            float4 x0 = ps[j0];
            float4 x1 = ps[j1];
            a0.x += x0.x; a0.y += x0.y; a0.z += x0.z; a0.w += x0.w;
            a1.x += x1.x; a1.y += x1.y; a1.z += x1.z; a1.w += x1.w;
            if (p2) {
                float4 x2 = ps[j2];
                a2.x += x2.x; a2.y += x2.y; a2.z += x2.z; a2.w += x2.w;
            }
        }
        const float sc = 1.0f / (float)SS;
        a0.x *= sc; a0.y *= sc; a0.z *= sc; a0.w *= sc;
        a1.x *= sc; a1.y *= sc; a1.z *= sc; a1.w *= sc;
        a2.x *= sc; a2.y *= sc; a2.z *= sc; a2.w *= sc;

        vt[ci * D4 + j0] = a0;
        vt[ci * D4 + j1] = a1;
        if (p2) vt[ci * D4 + j2] = a2;

#pragma unroll
        for (int k = 0; k < KK; k++) {
            uint2 u0 = cenh[k * D4 + j0];
            uint2 u1 = cenh[k * D4 + j1];
            float2 c00 = __half22float2(*reinterpret_cast<__half2*>(&u0.x));
            float2 c01 = __half22float2(*reinterpret_cast<__half2*>(&u0.y));
            float2 c10 = __half22float2(*reinterpret_cast<__half2*>(&u1.x));
            float2 c11 = __half22float2(*reinterpret_cast<__half2*>(&u1.y));
            float t = a0.x * c00.x + a0.y * c00.y + a0.z * c01.x + a0.w * c01.y
                    + a1.x * c10.x + a1.y * c10.y + a1.z * c11.x + a1.w * c11.y;
            if (p2) {
                uint2 u2 = cenh[k * D4 + j2];
                float2 c20 = __half22float2(*reinterpret_cast<__half2*>(&u2.x));
                float2 c21 = __half22float2(*reinterpret_cast<__half2*>(&u2.y));
                t += a2.x * c20.x + a2.y * c20.y + a2.z * c21.x + a2.w * c21.y;
            }
#pragma unroll
            for (int off = 16; off > 0; off >>= 1)
                t += __shfl_xor_sync(0xffffffffu, t, off);
            if (lane == 0)
                ew[k][ci] = __expf(t * RSQRT300);
        }
    }
    __syncthreads();

    // ---- pden partials ----
    if (threadIdx.x < KK) {
        const int k = threadIdx.x;
        float s = 0.f;
        for (int cc = 0; cc < cn; cc++) s += ew[k][cc];
        g_pden[(b * NSPLIT + tile) * KK + k] = s;
    }

    // ---- Phase B ----
    {
        const int t = threadIdx.x;
        if (t < D2) {
            float2 acc[KK];
#pragma unroll
            for (int k = 0; k < KK; k++) acc[k] = make_float2(0.f, 0.f);

            const float2* vf = reinterpret_cast<const float2*>(vt);
#pragma unroll 4
            for (int cc = 0; cc < cn; cc++) {
                float2 v2 = vf[cc * D2 + t];
#pragma unroll
                for (int k = 0; k < KK; k++) {
                    float al = ew[k][cc];
                    acc[k].x += al * v2.x;
                    acc[k].y += al * v2.y;
                }
            }
            float2* mp = reinterpret_cast<float2*>(g_mpart) + (size_t)((b * NSPLIT + tile) * KK) * D2;
#pragma unroll
            for (int k = 0; k < KK; k++) mp[k * D2 + t] = acc[k];
        }
    }

    // ---- Arrival: last tile-block of this b runs the epilogue ----
    __syncthreads();
    __shared__ int slast;
    if (threadIdx.x == 0) {
        __threadfence();   // publish this block's mpart/pden (release)
        unsigned old = atomicAdd(&g_cnt[b], 1u);
        slast = ((old & (NSPLIT - 1)) == (NSPLIT - 1)) ? 1 : 0;
    }
    __syncthreads();
    if (!slast) return;

    // ---- Epilogue (one block per b): similarity for all 8 k, warp per k ----
    __shared__ float ssv[KK];
    __shared__ float sq[KK];
    __shared__ int sidx;
    {
        const int k = w;   // 8 warps = 8 senses
        float num = 0.f, n1 = 0.f, n2 = 0.f;
        const float2* cp2 = reinterpret_cast<const float2*>(center + (size_t)(b * KK + k) * DD);
#pragma unroll
        for (int it = 0; it < 5; it++) {
            const int j = lane + it * 32;
            if (j < D2) {
                float2 cv = cp2[j];
                float2 mm = make_float2(0.f, 0.f);
#pragma unroll
                for (int s = 0; s < NSPLIT; s++) {
                    const float2* mp = reinterpret_cast<const float2*>(g_mpart)
                                     + (size_t)((b * NSPLIT + s) * KK + k) * D2;
                    float2 x = __ldcg(mp + j);   // bypass stale L1
                    mm.x += x.x; mm.y += x.y;
                }
                num += cv.x * mm.x + cv.y * mm.y;
                n1  += cv.x * cv.x + cv.y * cv.y;
                n2  += mm.x * mm.x + mm.y * mm.y;
            }
        }
#pragma unroll
        for (int off = 16; off > 0; off >>= 1) {
            num += __shfl_xor_sync(0xffffffffu, num, off);
            n1  += __shfl_xor_sync(0xffffffffu, n1, off);
            n2  += __shfl_xor_sync(0xffffffffu, n2, off);
        }
        if (lane == 0) {
            float dsum = 0.f;
#pragma unroll
            for (int s = 0; s < NSPLIT; s++)
                dsum += __ldcg(&g_pden[(b * NSPLIT + s) * KK + k]);
            float invd = 1.0f / dsum;
            float d1 = fmaxf(sqrtf(n1), 1e-8f);
            float d2 = fmaxf(sqrtf(n2) * invd, 1e-8f);
            ssv[k] = (num * invd) / (d1 * d2);
        }
    }
    __syncthreads();

    if (threadIdx.x == 0) {
        float mx = ssv[0]; int id = 0;
#pragma unroll
        for (int i = 1; i < KK; i++)
            if (ssv[i] > mx) { mx = ssv[i]; id = i; }
        float den = 0.f;
#pragma unroll
        for (int i = 0; i < KK; i++) den += __expf(ssv[i] - mx);
        float invden = 1.0f / den;
#pragma unroll
        for (int i = 0; i < KK; i++) sq[i] = __expf(ssv[i] - mx) * invden;
        sidx = id;
    }
    __syncthreads();

    if (threadIdx.x < KK)
        out[BB * DD + b * KK + threadIdx.x] = sq[threadIdx.x];
    if (threadIdx.x < D4) {
        const float4* src = reinterpret_cast<const float4*>(center + (size_t)(b * KK + sidx) * DD);
        float4* dst = reinterpret_cast<float4*>(out + (size_t)b * DD);
        dst[threadIdx.x] = src[threadIdx.x];
    }
}

// ---------------------------------------------------------------------------
extern "C" void kernel_launch(void* const* d_in, const int* in_sizes, int n_in,
                              void* d_out, int out_size) {
    // inputs: 0 center_pos(i32), 1 query_token_ids(i32) -- both mathematically dead
    //         2 center_sense_embeddings f32 [32,8,300]
    //         3 context_sense_embeddings f32 [32,511,8,300]
    const float* center = (const float*)d_in[2];
    const float* ctx    = (const float*)d_in[3];
    float* out = (float*)d_out;

    k_main<<<dim3(NSPLIT, BB), 256>>>(ctx, center, out);
}

// round 12
// speedup vs baseline: 1.0568x; 1.0568x over previous
#include <cuda_runtime.h>
#include <cuda_bf16.h>

// Shapes (fixed by setup_inputs): B=32, T=512, C=T-1=511, K=8, S=8, d=300
#define BB 32
#define CC 511
#define KK 8
#define SS 8
#define DD 300
#define D4 75      // DD/4 float4 per row
#define D2 150     // DD/2 float2 per row
#define ASTRIDE 512
#define NSPLIT2 8  // tail splits of 64 c; power of 2 for wrapping counter
#define RSQRT300 0.057735026918962576f

// Scratch (device globals; no allocation allowed)
__device__ float g_v[BB * CC * DD];                 // ~19.6 MB : v[b][c][d]
__device__ float g_a[BB * KK * ASTRIDE];            // a[b][k][c]
__device__ float g_pden[BB * NSPLIT2 * KK];         // partial sum of exp(a)
__device__ float g_mpart[BB * NSPLIT2 * KK * DD];   // partial unnormalized m'
__device__ unsigned g_cnt[BB];                      // wrapping counters

// ---------------------------------------------------------------------------
// Pass 1 — EXACT R4 structure (measured 33.9us @ 62.7% DRAM; do not perturb).
// grid (16, 32) = 512 blocks, block 256 (8 warps). Warp per c, 4 c each.
// v = mean_s(ctx) -> g_v (global, no reuse barrier); a = <center,v>/sqrt(d).
// ---------------------------------------------------------------------------
__global__ __launch_bounds__(256) void k_pass1(const float* __restrict__ ctx,
                                               const float* __restrict__ center) {
    const int b = blockIdx.y;
    const int tile = blockIdx.x;           // 32 c's per tile
    __shared__ float4 cen[KK * D4];        // 9600 B

    {
        const float4* cg = reinterpret_cast<const float4*>(center + (size_t)b * KK * DD);
        for (int i = threadIdx.x; i < KK * D4; i += blockDim.x) cen[i] = cg[i];
    }
    __syncthreads();

    const int w = threadIdx.x >> 5;
    const int lane = threadIdx.x & 31;
    const int j0 = lane, j1 = lane + 32, j2 = lane + 64;
    const bool p2 = (j2 < D4);

    int cend = tile * 32 + 32;
    if (cend > CC) cend = CC;

    for (int c = tile * 32 + w; c < cend; c += 8) {
        const float4* p = reinterpret_cast<const float4*>(ctx) + (size_t)(b * CC + c) * (SS * D4);
        float4 a0 = {0.f, 0.f, 0.f, 0.f}, a1 = a0, a2 = a0;
#pragma unroll
        for (int s = 0; s < SS; s++) {
            const float4* ps = p + s * D4;
            float4 x0 = ps[j0];
            float4 x1 = ps[j1];
            a0.x += x0.x; a0.y += x0.y; a0.z += x0.z; a0.w += x0.w;
            a1.x += x1.x; a1.y += x1.y; a1.z += x1.z; a1.w += x1.w;
            if (p2) {
                float4 x2 = ps[j2];
                a2.x += x2.x; a2.y += x2.y; a2.z += x2.z; a2.w += x2.w;
            }
        }
        const float sc = 1.0f / (float)SS;
        a0.x *= sc; a0.y *= sc; a0.z *= sc; a0.w *= sc;
        a1.x *= sc; a1.y *= sc; a1.z *= sc; a1.w *= sc;
        a2.x *= sc; a2.y *= sc; a2.z *= sc; a2.w *= sc;

        float4* vp = reinterpret_cast<float4*>(g_v) + (size_t)(b * CC + c) * D4;
        vp[j0] = a0;
        vp[j1] = a1;
        if (p2) vp[j2] = a2;

        float ak[KK];
#pragma unroll
        for (int k = 0; k < KK; k++) {
            float4 c0 = cen[k * D4 + j0];
            float4 c1 = cen[k * D4 + j1];
            float t = a0.x * c0.x + a0.y * c0.y + a0.z * c0.z + a0.w * c0.w
                    + a1.x * c1.x + a1.y * c1.y + a1.z * c1.z + a1.w * c1.w;
            if (p2) {
                float4 c2 = cen[k * D4 + j2];
                t += a2.x * c2.x + a2.y * c2.y + a2.z * c2.z + a2.w * c2.w;
            }
#pragma unroll
            for (int off = 16; off > 0; off >>= 1)
                t += __shfl_xor_sync(0xffffffffu, t, off);
            ak[k] = t;
        }
        if (lane == 0) {
#pragma unroll
            for (int k = 0; k < KK; k++)
                g_a[(size_t)(b * KK + k) * ASTRIDE + c] = ak[k] * RSQRT300;
        }
    }
}

// ---------------------------------------------------------------------------
// Tail: pass3 + sim + out in ONE kernel. grid (NSPLIT2=8, 32) = 256 blocks,
// block 256. Each block: exp weights for its 64 c's, partial m' + pden,
// then arrival counter; the 8th block for b computes cosine sims (warp per
// k) from L2-hot partials, softmax/argmax, and writes the outputs.
// ---------------------------------------------------------------------------
__global__ __launch_bounds__(256) void k_tail(const float* __restrict__ center,
                                              float* __restrict__ out) {
    const int split = blockIdx.x;
    const int b = blockIdx.y;
    const int c0 = split * 64;
    int cn = CC - c0; if (cn > 64) cn = 64;

    const int w = threadIdx.x >> 5;
    const int lane = threadIdx.x & 31;

    __shared__ float ew[KK][64];

    for (int i = threadIdx.x; i < KK * 64; i += blockDim.x) {
        int k = i >> 6, cc = i & 63;
        float val = 0.f;
        if (cc < cn)
            val = __expf(g_a[(size_t)(b * KK + k) * ASTRIDE + c0 + cc]);
        ew[k][cc] = val;
    }
    __syncthreads();

    // pden partials
    if (threadIdx.x < KK) {
        const int k = threadIdx.x;
        float s = 0.f;
#pragma unroll 8
        for (int cc = 0; cc < 64; cc++) s += ew[k][cc];
        g_pden[(b * NSPLIT2 + split) * KK + k] = s;
    }

    // partial m' accumulation: thread per float2 of d
    {
        const int t = threadIdx.x;
        if (t < D2) {
            float2 acc[KK];
#pragma unroll
            for (int k = 0; k < KK; k++) acc[k] = make_float2(0.f, 0.f);

            const float2* vb = reinterpret_cast<const float2*>(g_v) + (size_t)(b * CC + c0) * D2 + t;
#pragma unroll 4
            for (int cc = 0; cc < cn; cc++) {
                float2 v2 = vb[(size_t)cc * D2];
#pragma unroll
                for (int k = 0; k < KK; k++) {
                    float al = ew[k][cc];
                    acc[k].x += al * v2.x;
                    acc[k].y += al * v2.y;
                }
            }
            float2* mp = reinterpret_cast<float2*>(g_mpart) + (size_t)((b * NSPLIT2 + split) * KK) * D2;
#pragma unroll
            for (int k = 0; k < KK; k++) mp[k * D2 + t] = acc[k];
        }
    }

    // arrival; last block of this b runs the epilogue
    __syncthreads();
    __shared__ int slast;
    if (threadIdx.x == 0) {
        __threadfence();   // publish mpart/pden (release)
        unsigned old = atomicAdd(&g_cnt[b], 1u);
        slast = ((old & (NSPLIT2 - 1)) == (NSPLIT2 - 1)) ? 1 : 0;
    }
    __syncthreads();
    if (!slast) return;

    // ---- epilogue: cosine sim for all 8 k (warp per k) ----
    __shared__ float ssv[KK];
    __shared__ float sq[KK];
    __shared__ int sidx;
    {
        const int k = w;
        float num = 0.f, n1 = 0.f, n2 = 0.f;
        const float2* cp2 = reinterpret_cast<const float2*>(center + (size_t)(b * KK + k) * DD);
#pragma unroll
        for (int it = 0; it < 5; it++) {
            const int j = lane + it * 32;
            if (j < D2) {
                float2 cv = cp2[j];
                float2 mm = make_float2(0.f, 0.f);
#pragma unroll
                for (int s = 0; s < NSPLIT2; s++) {
                    const float2* mp = reinterpret_cast<const float2*>(g_mpart)
                                     + (size_t)((b * NSPLIT2 + s) * KK + k) * D2;
                    float2 x = __ldcg(mp + j);   // bypass stale L1
                    mm.x += x.x; mm.y += x.y;
                }
                num += cv.x * mm.x + cv.y * mm.y;
                n1  += cv.x * cv.x + cv.y * cv.y;
                n2  += mm.x * mm.x + mm.y * mm.y;
            }
        }
#pragma unroll
        for (int off = 16; off > 0; off >>= 1) {
            num += __shfl_xor_sync(0xffffffffu, num, off);
            n1  += __shfl_xor_sync(0xffffffffu, n1, off);
            n2  += __shfl_xor_sync(0xffffffffu, n2, off);
        }
        if (lane == 0) {
            float dsum = 0.f;
#pragma unroll
            for (int s = 0; s < NSPLIT2; s++)
                dsum += __ldcg(&g_pden[(b * NSPLIT2 + s) * KK + k]);
            float invd = 1.0f / dsum;
            float d1 = fmaxf(sqrtf(n1), 1e-8f);
            float d2 = fmaxf(sqrtf(n2) * invd, 1e-8f);
            ssv[k] = (num * invd) / (d1 * d2);
        }
    }
    __syncthreads();

    if (threadIdx.x == 0) {
        float mx = ssv[0]; int id = 0;
#pragma unroll
        for (int i = 1; i < KK; i++)
            if (ssv[i] > mx) { mx = ssv[i]; id = i; }
        float den = 0.f;
#pragma unroll
        for (int i = 0; i < KK; i++) den += __expf(ssv[i] - mx);
        float invden = 1.0f / den;
#pragma unroll
        for (int i = 0; i < KK; i++) sq[i] = __expf(ssv[i] - mx) * invden;
        sidx = id;
    }
    __syncthreads();

    if (threadIdx.x < KK)
        out[BB * DD + b * KK + threadIdx.x] = sq[threadIdx.x];
    if (threadIdx.x < D4) {
        const float4* src = reinterpret_cast<const float4*>(center + (size_t)(b * KK + sidx) * DD);
        float4* dst = reinterpret_cast<float4*>(out + (size_t)b * DD);
        dst[threadIdx.x] = src[threadIdx.x];
    }
}

// ---------------------------------------------------------------------------
extern "C" void kernel_launch(void* const* d_in, const int* in_sizes, int n_in,
                              void* d_out, int out_size) {
    // inputs: 0 center_pos(i32), 1 query_token_ids(i32) -- both mathematically dead
    //         2 center_sense_embeddings f32 [32,8,300]
    //         3 context_sense_embeddings f32 [32,511,8,300]
    const float* center = (const float*)d_in[2];
    const float* ctx    = (const float*)d_in[3];
    float* out = (float*)d_out;

    k_pass1<<<dim3(16, BB), 256>>>(ctx, center);
    k_tail<<<dim3(NSPLIT2, BB), 256>>>(center, out);
}

// round 13
// speedup vs baseline: 1.1512x; 1.0893x over previous
#include <cuda_runtime.h>
#include <cuda_bf16.h>

// Shapes (fixed by setup_inputs): B=32, T=512, C=T-1=511, K=8, S=8, d=300
#define BB 32
#define CC 511
#define KK 8
#define SS 8
#define DD 300
#define D4 75      // DD/4 float4 per row
#define D2 150     // DD/2 float2 per row
#define ASTRIDE 512
#define NSPLIT2 16 // tail splits of 32 c; power of 2 for wrapping counter
#define TAILTHREADS 320
#define RSQRT300 0.057735026918962576f

// Scratch (device globals; no allocation allowed)
__device__ float g_v[BB * CC * DD];                 // ~19.6 MB : v[b][c][d]
__device__ float g_a[BB * KK * ASTRIDE];            // a[b][k][c]
__device__ float g_pden[BB * NSPLIT2 * KK];         // partial sum of exp(a)
__device__ float g_mpart[BB * NSPLIT2 * KK * DD];   // partial unnormalized m'
__device__ unsigned g_cnt[BB];                      // wrapping counters

// ---------------------------------------------------------------------------
// Pass 1 — EXACT R4/R12 structure (28.7us measured; do not perturb).
// grid (16, 32) = 512 blocks, block 256 (8 warps). Warp per c, 4 c each.
// ---------------------------------------------------------------------------
__global__ __launch_bounds__(256) void k_pass1(const float* __restrict__ ctx,
                                               const float* __restrict__ center) {
    const int b = blockIdx.y;
    const int tile = blockIdx.x;           // 32 c's per tile
    __shared__ float4 cen[KK * D4];        // 9600 B

    {
        const float4* cg = reinterpret_cast<const float4*>(center + (size_t)b * KK * DD);
        for (int i = threadIdx.x; i < KK * D4; i += blockDim.x) cen[i] = cg[i];
    }
    __syncthreads();

    const int w = threadIdx.x >> 5;
    const int lane = threadIdx.x & 31;
    const int j0 = lane, j1 = lane + 32, j2 = lane + 64;
    const bool p2 = (j2 < D4);

    int cend = tile * 32 + 32;
    if (cend > CC) cend = CC;

    for (int c = tile * 32 + w; c < cend; c += 8) {
        const float4* p = reinterpret_cast<const float4*>(ctx) + (size_t)(b * CC + c) * (SS * D4);
        float4 a0 = {0.f, 0.f, 0.f, 0.f}, a1 = a0, a2 = a0;
#pragma unroll
        for (int s = 0; s < SS; s++) {
            const float4* ps = p + s * D4;
            float4 x0 = ps[j0];
            float4 x1 = ps[j1];
            a0.x += x0.x; a0.y += x0.y; a0.z += x0.z; a0.w += x0.w;
            a1.x += x1.x; a1.y += x1.y; a1.z += x1.z; a1.w += x1.w;
            if (p2) {
                float4 x2 = ps[j2];
                a2.x += x2.x; a2.y += x2.y; a2.z += x2.z; a2.w += x2.w;
            }
        }
        const float sc = 1.0f / (float)SS;
        a0.x *= sc; a0.y *= sc; a0.z *= sc; a0.w *= sc;
        a1.x *= sc; a1.y *= sc; a1.z *= sc; a1.w *= sc;
        a2.x *= sc; a2.y *= sc; a2.z *= sc; a2.w *= sc;

        float4* vp = reinterpret_cast<float4*>(g_v) + (size_t)(b * CC + c) * D4;
        vp[j0] = a0;
        vp[j1] = a1;
        if (p2) vp[j2] = a2;

        float ak[KK];
#pragma unroll
        for (int k = 0; k < KK; k++) {
            float4 c0 = cen[k * D4 + j0];
            float4 c1 = cen[k * D4 + j1];
            float t = a0.x * c0.x + a0.y * c0.y + a0.z * c0.z + a0.w * c0.w
                    + a1.x * c1.x + a1.y * c1.y + a1.z * c1.z + a1.w * c1.w;
            if (p2) {
                float4 c2 = cen[k * D4 + j2];
                t += a2.x * c2.x + a2.y * c2.y + a2.z * c2.z + a2.w * c2.w;
            }
#pragma unroll
            for (int off = 16; off > 0; off >>= 1)
                t += __shfl_xor_sync(0xffffffffu, t, off);
            ak[k] = t;
        }
        if (lane == 0) {
#pragma unroll
            for (int k = 0; k < KK; k++)
                g_a[(size_t)(b * KK + k) * ASTRIDE + c] = ak[k] * RSQRT300;
        }
    }
}

// ---------------------------------------------------------------------------
// Tail: pass3 + sim + out in ONE kernel.
// grid (NSPLIT2=16, 32) = 512 blocks, block 320 (10 warps).
// One float of d per thread (300/320 active) -> 2x active load threads and
// scalar acc[8] (low regs) vs R12's float2/150-thread variant. Last block
// per b (wrapping counter) does cosine sims + softmax/argmax + outputs.
// ---------------------------------------------------------------------------
__global__ __launch_bounds__(TAILTHREADS) void k_tail(const float* __restrict__ center,
                                                      float* __restrict__ out) {
    const int split = blockIdx.x;
    const int b = blockIdx.y;
    const int c0 = split * 32;
    int cn = CC - c0; if (cn > 32) cn = 32;

    const int w = threadIdx.x >> 5;
    const int lane = threadIdx.x & 31;

    __shared__ float ew[KK][32];

    // exp weights: 256 entries, one per thread
    if (threadIdx.x < KK * 32) {
        const int k = threadIdx.x >> 5, cc = threadIdx.x & 31;
        float val = 0.f;
        if (cc < cn)
            val = __expf(g_a[(size_t)(b * KK + k) * ASTRIDE + c0 + cc]);
        ew[k][cc] = val;
    }
    __syncthreads();

    // pden partials
    if (threadIdx.x < KK) {
        const int k = threadIdx.x;
        float s = 0.f;
#pragma unroll 8
        for (int cc = 0; cc < 32; cc++) s += ew[k][cc];
        g_pden[(b * NSPLIT2 + split) * KK + k] = s;
    }

    // partial m': one float of d per thread
    {
        const int t = threadIdx.x;
        if (t < DD) {
            float acc[KK];
#pragma unroll
            for (int k = 0; k < KK; k++) acc[k] = 0.f;

            const float* vb = g_v + (size_t)(b * CC + c0) * DD + t;
#pragma unroll 4
            for (int cc = 0; cc < cn; cc++) {
                float v = vb[(size_t)cc * DD];
#pragma unroll
                for (int k = 0; k < KK; k++)
                    acc[k] += ew[k][cc] * v;
            }
            float* mp = g_mpart + (size_t)((b * NSPLIT2 + split) * KK) * DD;
#pragma unroll
            for (int k = 0; k < KK; k++) mp[k * DD + t] = acc[k];
        }
    }

    // arrival; last block of this b runs the epilogue
    __syncthreads();
    __shared__ int slast;
    if (threadIdx.x == 0) {
        __threadfence();   // publish mpart/pden (release)
        unsigned old = atomicAdd(&g_cnt[b], 1u);
        slast = ((old & (NSPLIT2 - 1)) == (NSPLIT2 - 1)) ? 1 : 0;
    }
    __syncthreads();
    if (!slast) return;

    // ---- epilogue: cosine sim for all 8 k (warp per k, warps 0..7) ----
    __shared__ float ssv[KK];
    __shared__ float sq[KK];
    __shared__ int sidx;
    if (w < KK) {
        const int k = w;
        float num = 0.f, n1 = 0.f, n2 = 0.f;
        const float2* cp2 = reinterpret_cast<const float2*>(center + (size_t)(b * KK + k) * DD);
#pragma unroll
        for (int it = 0; it < 5; it++) {
            const int j = lane + it * 32;
            if (j < D2) {
                float2 cv = cp2[j];
                float2 mm = make_float2(0.f, 0.f);
#pragma unroll
                for (int s = 0; s < NSPLIT2; s++) {
                    const float2* mp = reinterpret_cast<const float2*>(g_mpart)
                                     + (size_t)((b * NSPLIT2 + s) * KK + k) * D2;
                    float2 x = __ldcg(mp + j);   // bypass stale L1
                    mm.x += x.x; mm.y += x.y;
                }
                num += cv.x * mm.x + cv.y * mm.y;
                n1  += cv.x * cv.x + cv.y * cv.y;
                n2  += mm.x * mm.x + mm.y * mm.y;
            }
        }
#pragma unroll
        for (int off = 16; off > 0; off >>= 1) {
            num += __shfl_xor_sync(0xffffffffu, num, off);
            n1  += __shfl_xor_sync(0xffffffffu, n1, off);
            n2  += __shfl_xor_sync(0xffffffffu, n2, off);
        }
        if (lane == 0) {
            float dsum = 0.f;
#pragma unroll
            for (int s = 0; s < NSPLIT2; s++)
                dsum += __ldcg(&g_pden[(b * NSPLIT2 + s) * KK + k]);
            float invd = 1.0f / dsum;
            float d1 = fmaxf(sqrtf(n1), 1e-8f);
            float d2 = fmaxf(sqrtf(n2) * invd, 1e-8f);
            ssv[k] = (num * invd) / (d1 * d2);
        }
    }
    __syncthreads();

    if (threadIdx.x == 0) {
        float mx = ssv[0]; int id = 0;
#pragma unroll
        for (int i = 1; i < KK; i++)
            if (ssv[i] > mx) { mx = ssv[i]; id = i; }
        float den = 0.f;
#pragma unroll
        for (int i = 0; i < KK; i++) den += __expf(ssv[i] - mx);
        float invden = 1.0f / den;
#pragma unroll
        for (int i = 0; i < KK; i++) sq[i] = __expf(ssv[i] - mx) * invden;
        sidx = id;
    }
    __syncthreads();

    if (threadIdx.x < KK)
        out[BB * DD + b * KK + threadIdx.x] = sq[threadIdx.x];
    if (threadIdx.x < D4) {
        const float4* src = reinterpret_cast<const float4*>(center + (size_t)(b * KK + sidx) * DD);
        float4* dst = reinterpret_cast<float4*>(out + (size_t)b * DD);
        dst[threadIdx.x] = src[threadIdx.x];
    }
}

// ---------------------------------------------------------------------------
extern "C" void kernel_launch(void* const* d_in, const int* in_sizes, int n_in,
                              void* d_out, int out_size) {
    // inputs: 0 center_pos(i32), 1 query_token_ids(i32) -- both mathematically dead
    //         2 center_sense_embeddings f32 [32,8,300]
    //         3 context_sense_embeddings f32 [32,511,8,300]
    const float* center = (const float*)d_in[2];
    const float* ctx    = (const float*)d_in[3];
    float* out = (float*)d_out;

    k_pass1<<<dim3(16, BB), 256>>>(ctx, center);
    k_tail<<<dim3(NSPLIT2, BB), TAILTHREADS>>>(center, out);
}

// round 14
// speedup vs baseline: 1.2470x; 1.0832x over previous
#include <cuda_runtime.h>
#include <cuda_bf16.h>

// Shapes (fixed by setup_inputs): B=32, T=512, C=T-1=511, K=8, S=8, d=300
#define BB 32
#define CC 511
#define KK 8
#define SS 8
#define DD 300
#define D4 75      // DD/4 float4 per row
#define D2 150     // DD/2 float2 per row
#define ASTRIDE 512
#define NSPLIT2 16 // tail splits of 32 c; power of 2 for wrapping counter
#define TAILTHREADS 320
#define RSQRT300 0.057735026918962576f

// Scratch (device globals; no allocation allowed)
// g_v padded by one row: the last tail split reads row (b*CC + 511) with
// weight 0 -- padding keeps that read in-bounds.
__device__ float g_v[BB * CC * DD + DD];
__device__ float g_a[BB * KK * ASTRIDE];            // a[b][k][c]
__device__ float g_pden[BB * NSPLIT2 * KK];         // partial sum of exp(a)
__device__ float g_mpart[BB * NSPLIT2 * KK * DD];   // partial unnormalized m'
__device__ unsigned g_cnt[BB];                      // wrapping counters

// ---------------------------------------------------------------------------
// Pass 1 — proven R4/R12 structure; ONLY change: ctx loads use __ldcs
// (evict-first). ctx is read exactly once; keeping it out of L2 lets the
// 19.6MB g_v stay L2-resident for the tail kernel.
// grid (16, 32) = 512 blocks, block 256 (8 warps). Warp per c, 4 c each.
// ---------------------------------------------------------------------------
__global__ __launch_bounds__(256) void k_pass1(const float* __restrict__ ctx,
                                               const float* __restrict__ center) {
    const int b = blockIdx.y;
    const int tile = blockIdx.x;           // 32 c's per tile
    __shared__ float4 cen[KK * D4];        // 9600 B

    {
        const float4* cg = reinterpret_cast<const float4*>(center + (size_t)b * KK * DD);
        for (int i = threadIdx.x; i < KK * D4; i += blockDim.x) cen[i] = cg[i];
    }
    __syncthreads();

    const int w = threadIdx.x >> 5;
    const int lane = threadIdx.x & 31;
    const int j0 = lane, j1 = lane + 32, j2 = lane + 64;
    const bool p2 = (j2 < D4);

    int cend = tile * 32 + 32;
    if (cend > CC) cend = CC;

    for (int c = tile * 32 + w; c < cend; c += 8) {
        const float4* p = reinterpret_cast<const float4*>(ctx) + (size_t)(b * CC + c) * (SS * D4);
        float4 a0 = {0.f, 0.f, 0.f, 0.f}, a1 = a0, a2 = a0;
#pragma unroll
        for (int s = 0; s < SS; s++) {
            const float4* ps = p + s * D4;
            float4 x0 = __ldcs(ps + j0);
            float4 x1 = __ldcs(ps + j1);
            a0.x += x0.x; a0.y += x0.y; a0.z += x0.z; a0.w += x0.w;
            a1.x += x1.x; a1.y += x1.y; a1.z += x1.z; a1.w += x1.w;
            if (p2) {
                float4 x2 = __ldcs(ps + j2);
                a2.x += x2.x; a2.y += x2.y; a2.z += x2.z; a2.w += x2.w;
            }
        }
        const float sc = 1.0f / (float)SS;
        a0.x *= sc; a0.y *= sc; a0.z *= sc; a0.w *= sc;
        a1.x *= sc; a1.y *= sc; a1.z *= sc; a1.w *= sc;
        a2.x *= sc; a2.y *= sc; a2.z *= sc; a2.w *= sc;

        float4* vp = reinterpret_cast<float4*>(g_v) + (size_t)(b * CC + c) * D4;
        vp[j0] = a0;
        vp[j1] = a1;
        if (p2) vp[j2] = a2;

        float ak[KK];
#pragma unroll
        for (int k = 0; k < KK; k++) {
            float4 c0 = cen[k * D4 + j0];
            float4 c1 = cen[k * D4 + j1];
            float t = a0.x * c0.x + a0.y * c0.y + a0.z * c0.z + a0.w * c0.w
                    + a1.x * c1.x + a1.y * c1.y + a1.z * c1.z + a1.w * c1.w;
            if (p2) {
                float4 c2 = cen[k * D4 + j2];
                t += a2.x * c2.x + a2.y * c2.y + a2.z * c2.z + a2.w * c2.w;
            }
#pragma unroll
            for (int off = 16; off > 0; off >>= 1)
                t += __shfl_xor_sync(0xffffffffu, t, off);
            ak[k] = t;
        }
        if (lane == 0) {
#pragma unroll
            for (int k = 0; k < KK; k++)
                g_a[(size_t)(b * KK + k) * ASTRIDE + c] = ak[k] * RSQRT300;
        }
    }
}

// ---------------------------------------------------------------------------
// Tail: pass3 + sim + out in ONE kernel.
// grid (NSPLIT2=16, 32) = 512 blocks, block 320 (10 warps).
// One float of d per thread; cc-loop is a COMPILE-TIME 32 (boundary handled
// by ew=0 zero weights + padded g_v) so the compiler can batch loads (MLP 8).
// Last block per b (wrapping counter) does cosine sims + softmax + outputs.
// ---------------------------------------------------------------------------
__global__ __launch_bounds__(TAILTHREADS) void k_tail(const float* __restrict__ center,
                                                      float* __restrict__ out) {
    const int split = blockIdx.x;
    const int b = blockIdx.y;
    const int c0 = split * 32;
    const int cn = (CC - c0 < 32) ? (CC - c0) : 32;

    const int w = threadIdx.x >> 5;
    const int lane = threadIdx.x & 31;

    __shared__ float ew[KK][32];

    // exp weights: 256 entries, one per thread; zero outside cn
    if (threadIdx.x < KK * 32) {
        const int k = threadIdx.x >> 5, cc = threadIdx.x & 31;
        float val = 0.f;
        if (cc < cn)
            val = __expf(g_a[(size_t)(b * KK + k) * ASTRIDE + c0 + cc]);
        ew[k][cc] = val;
    }
    __syncthreads();

    // pden partials
    if (threadIdx.x < KK) {
        const int k = threadIdx.x;
        float s = 0.f;
#pragma unroll
        for (int cc = 0; cc < 32; cc++) s += ew[k][cc];
        g_pden[(b * NSPLIT2 + split) * KK + k] = s;
    }

    // partial m': one float of d per thread; fixed 32-iteration loop
    {
        const int t = threadIdx.x;
        if (t < DD) {
            float acc[KK];
#pragma unroll
            for (int k = 0; k < KK; k++) acc[k] = 0.f;

            const float* vb = g_v + (size_t)(b * CC + c0) * DD + t;
#pragma unroll 8
            for (int cc = 0; cc < 32; cc++) {
                float v = vb[(size_t)cc * DD];   // weight 0 past cn (padded g_v)
#pragma unroll
                for (int k = 0; k < KK; k++)
                    acc[k] += ew[k][cc] * v;
            }
            float* mp = g_mpart + (size_t)((b * NSPLIT2 + split) * KK) * DD;
#pragma unroll
            for (int k = 0; k < KK; k++) mp[k * DD + t] = acc[k];
        }
    }

    // arrival; last block of this b runs the epilogue
    __syncthreads();
    __shared__ int slast;
    if (threadIdx.x == 0) {
        __threadfence();   // publish mpart/pden (release)
        unsigned old = atomicAdd(&g_cnt[b], 1u);
        slast = ((old & (NSPLIT2 - 1)) == (NSPLIT2 - 1)) ? 1 : 0;
    }
    __syncthreads();
    if (!slast) return;

    // ---- epilogue: cosine sim for all 8 k (warp per k, warps 0..7) ----
    __shared__ float ssv[KK];
    __shared__ float sq[KK];
    __shared__ int sidx;
    if (w < KK) {
        const int k = w;
        float num = 0.f, n1 = 0.f, n2 = 0.f;
        const float2* cp2 = reinterpret_cast<const float2*>(center + (size_t)(b * KK + k) * DD);
#pragma unroll
        for (int it = 0; it < 5; it++) {
            const int j = lane + it * 32;
            if (j < D2) {
                float2 cv = cp2[j];
                float2 mm = make_float2(0.f, 0.f);
#pragma unroll
                for (int s = 0; s < NSPLIT2; s++) {
                    const float2* mp = reinterpret_cast<const float2*>(g_mpart)
                                     + (size_t)((b * NSPLIT2 + s) * KK + k) * D2;
                    float2 x = __ldcg(mp + j);   // bypass stale L1
                    mm.x += x.x; mm.y += x.y;
                }
                num += cv.x * mm.x + cv.y * mm.y;
                n1  += cv.x * cv.x + cv.y * cv.y;
                n2  += mm.x * mm.x + mm.y * mm.y;
            }
        }
#pragma unroll
        for (int off = 16; off > 0; off >>= 1) {
            num += __shfl_xor_sync(0xffffffffu, num, off);
            n1  += __shfl_xor_sync(0xffffffffu, n1, off);
            n2  += __shfl_xor_sync(0xffffffffu, n2, off);
        }
        if (lane == 0) {
            float dsum = 0.f;
#pragma unroll
            for (int s = 0; s < NSPLIT2; s++)
                dsum += __ldcg(&g_pden[(b * NSPLIT2 + s) * KK + k]);
            float invd = 1.0f / dsum;
            float d1 = fmaxf(sqrtf(n1), 1e-8f);
            float d2 = fmaxf(sqrtf(n2) * invd, 1e-8f);
            ssv[k] = (num * invd) / (d1 * d2);
        }
    }
    __syncthreads();

    if (threadIdx.x == 0) {
        float mx = ssv[0]; int id = 0;
#pragma unroll
        for (int i = 1; i < KK; i++)
            if (ssv[i] > mx) { mx = ssv[i]; id = i; }
        float den = 0.f;
#pragma unroll
        for (int i = 0; i < KK; i++) den += __expf(ssv[i] - mx);
        float invden = 1.0f / den;
#pragma unroll
        for (int i = 0; i < KK; i++) sq[i] = __expf(ssv[i] - mx) * invden;
        sidx = id;
    }
    __syncthreads();

    if (threadIdx.x < KK)
        out[BB * DD + b * KK + threadIdx.x] = sq[threadIdx.x];
    if (threadIdx.x < D4) {
        const float4* src = reinterpret_cast<const float4*>(center + (size_t)(b * KK + sidx) * DD);
        float4* dst = reinterpret_cast<float4*>(out + (size_t)b * DD);
        dst[threadIdx.x] = src[threadIdx.x];
    }
}

// ---------------------------------------------------------------------------
extern "C" void kernel_launch(void* const* d_in, const int* in_sizes, int n_in,
                              void* d_out, int out_size) {
    // inputs: 0 center_pos(i32), 1 query_token_ids(i32) -- both mathematically dead
    //         2 center_sense_embeddings f32 [32,8,300]
    //         3 context_sense_embeddings f32 [32,511,8,300]
    const float* center = (const float*)d_in[2];
    const float* ctx    = (const float*)d_in[3];
    float* out = (float*)d_out;

    k_pass1<<<dim3(16, BB), 256>>>(ctx, center);
    k_tail<<<dim3(NSPLIT2, BB), TAILTHREADS>>>(center, out);
}